// round 3
// baseline (speedup 1.0000x reference)
#include <cuda_runtime.h>

// TemporalAttention_43722767073503
//
// The reference ends with log_softmax over the last axis of the score tensor,
// whose shape is (B, T, 1) = (256, 2048, 1). log_softmax over a size-1 axis is
// identically 0 for any finite input (x - logsumexp(x) = x - x = 0). All
// inputs are finite random normals/uniforms, so the exact output is 524288
// zeros. Both GEMMs, the tanh, and the v-projection are dead code. The optimal
// kernel is a vectorized zero-fill of d_out.
//
// Single launch, grid-stride over float4 chunks, scalar tail handled in the
// same kernel (out_size here is 524288, divisible by 4, so the tail is empty;
// the guard is for robustness only).

__global__ void zero_out_kernel(float* __restrict__ out, int n) {
    int n4 = n >> 2;
    float4* __restrict__ out4 = reinterpret_cast<float4*>(out);
    const float4 z = make_float4(0.f, 0.f, 0.f, 0.f);
    for (int i = blockIdx.x * blockDim.x + threadIdx.x; i < n4;
         i += gridDim.x * blockDim.x) {
        out4[i] = z;
    }
    // scalar tail (0..3 elements)
    int tail_start = n4 << 2;
    int t = tail_start + blockIdx.x * blockDim.x + threadIdx.x;
    if (t < n) {
        out[t] = 0.f;
    }
}

extern "C" void kernel_launch(void* const* d_in, const int* in_sizes, int n_in,
                              void* d_out, int out_size) {
    (void)d_in; (void)in_sizes; (void)n_in;
    const int threads = 256;
    int n4 = out_size >> 2;
    int blocks = (n4 + threads - 1) / threads;
    if (blocks < 1) blocks = 1;
    if (blocks > 1024) blocks = 1024;   // grid-stride covers the rest
    zero_out_kernel<<<blocks, threads>>>((float*)d_out, out_size);
}